// round 2
// baseline (speedup 1.0000x reference)
#include <cuda_runtime.h>

// Problem constants
#define B_      32
#define C_      8
#define H_      224
#define W_      224
#define E_      768
#define P_      16
#define HP_     14          // H/P
#define NPATCH  196         // HP*HP
#define NSEG    32
#define K_      256         // P*P
#define M_      (B_*C_*NPATCH)  // 50176

// Static device scratch (allocation-free contract)
__device__ float g_Wt[K_*E_];       // proj_w transposed: Wt[k][e]
__device__ float g_CtxT[E_*E_];     // ctx_w transposed:  CtxT[f][e]
__device__ float g_xsum[NSEG*K_];   // segment sums of xbar
__device__ float g_cnt[NSEG];       // segment counts
__device__ float g_ctx[NSEG*E_];    // per-segment context vector

// ---------------------------------------------------------------------------
// Zero accumulators + build segment counts. Single block.
__global__ void k_init(const int* __restrict__ cidx) {
    int t = threadIdx.x;
    for (int i = t; i < NSEG*K_; i += 256) g_xsum[i] = 0.f;
    if (t < NSEG) g_cnt[t] = 0.f;
    __syncthreads();
    if (t < B_*C_) atomicAdd(&g_cnt[cidx[t] & (NSEG-1)], 1.0f);
}

// ---------------------------------------------------------------------------
// Generic 32x32 tiled transpose: dst[c*R + r] = src[r*C + c]
// which==0 -> g_Wt (proj_w: R=768,C=256), which==1 -> g_CtxT (ctx_w: R=768,C=768)
__global__ void k_tr(const float* __restrict__ src, int R, int Ccols, int which) {
    __shared__ float tile[32][33];
    float* dst = (which == 0) ? g_Wt : g_CtxT;
    int r0 = blockIdx.y * 32, c0 = blockIdx.x * 32;
    int tx = threadIdx.x, ty = threadIdx.y;   // 32 x 8
    #pragma unroll
    for (int i = 0; i < 32; i += 8)
        tile[ty+i][tx] = src[(size_t)(r0+ty+i)*Ccols + c0 + tx];
    __syncthreads();
    #pragma unroll
    for (int i = 0; i < 32; i += 8)
        dst[(size_t)(c0+ty+i)*R + r0 + tx] = tile[tx][ty+i];
}

// ---------------------------------------------------------------------------
// Per-(b,c) mean over the 196 patches of each (p,q) pixel position, then
// segment-accumulate into g_xsum[seg]. One block per (b,c), 256 threads.
__global__ void k_xbar(const float* __restrict__ x, const int* __restrict__ cidx) {
    int bc = blockIdx.x;
    int t = threadIdx.x;           // t = p*16 + q
    int p = t >> 4, q = t & 15;
    const float* base = x + (size_t)bc * H_ * W_ + p * W_ + q;
    float s = 0.f;
    #pragma unroll 2
    for (int hp = 0; hp < HP_; hp++)
        #pragma unroll
        for (int wp = 0; wp < HP_; wp++)
            s += base[(hp*P_)*W_ + wp*P_];
    s *= (1.0f / (float)NPATCH);
    int seg = cidx[bc] & (NSEG-1);
    atomicAdd(&g_xsum[seg*K_ + t], s);
}

// ---------------------------------------------------------------------------
// Per-segment: means = (xsum/cnt) @ Wt + proj_b ; ctx = means @ ctx_w^T + ctx_b
// One block per segment, 768 threads.
__global__ void k_ctx(const float* __restrict__ proj_b, const float* __restrict__ ctx_b) {
    int s = blockIdx.x, t = threadIdx.x;
    __shared__ float xm[K_];
    __shared__ float mu[E_];
    if (t < K_) {
        float cn = fmaxf(g_cnt[s], 1.0f);
        xm[t] = g_xsum[s*K_ + t] / cn;
    }
    __syncthreads();
    float d = 0.f;
    #pragma unroll 4
    for (int k = 0; k < K_; k++) d += xm[k] * g_Wt[k*E_ + t];   // coalesced across t
    mu[t] = d + proj_b[t];
    __syncthreads();
    float c = 0.f;
    #pragma unroll 4
    for (int f = 0; f < E_; f++) c += mu[f] * g_CtxT[f*E_ + t]; // coalesced across t
    g_ctx[s*E_ + t] = c + ctx_b[t];
}

// ---------------------------------------------------------------------------
// Main fused patchify GEMM + bias + ctx broadcast epilogue.
// out[m, e] = sum_k patch[m,k]*Wt[k,e] + proj_b[e] + ctx[seg(m), e]
// M=50176 (exactly 392*128), N=768 (exactly 6*128), K=256 (exactly 16*16).
#define BM 128
#define BN 128
#define BK 16
__global__ __launch_bounds__(256, 2)
void k_gemm(const float* __restrict__ x, const int* __restrict__ cidx,
            const float* __restrict__ proj_b, float* __restrict__ out) {
    __shared__ float As[BK][BM + 4];   // stride 132, 16B-aligned rows
    __shared__ float Bs[BK][BN];
    __shared__ int rowoff[BM];
    __shared__ int segrow[BM];

    int m0 = blockIdx.y * BM;
    int e0 = blockIdx.x * BN;
    int t  = threadIdx.x;
    int tx = t & 15, ty = t >> 4;

    if (t < BM) {
        int m  = m0 + t;
        int b  = m / (C_ * NPATCH);
        int n  = m - b * (C_ * NPATCH);
        int c  = n / NPATCH;
        int r  = n - c * NPATCH;
        int hp = r / HP_;
        int wp = r - hp * HP_;
        rowoff[t] = ((b * C_ + c) * H_ + hp * P_) * W_ + wp * P_;
        segrow[t] = cidx[m / NPATCH] & (NSEG-1);   // m/196 = b*C+c
    }
    __syncthreads();

    float acc[8][8];
    #pragma unroll
    for (int i = 0; i < 8; i++)
        #pragma unroll
        for (int j = 0; j < 8; j++) acc[i][j] = 0.f;

    // k-chunk kk covers p = kk, q = 0..15 : 16 contiguous floats per row
    for (int kk = 0; kk < K_/BK; kk++) {
        #pragma unroll
        for (int i = 0; i < 2; i++) {   // A tile: 512 float4 / 256 threads
            int idx = t + i*256;
            int row = idx >> 2, qv = idx & 3;
            float4 v = *(const float4*)(x + rowoff[row] + kk * W_ + qv * 4);
            As[qv*4+0][row] = v.x; As[qv*4+1][row] = v.y;
            As[qv*4+2][row] = v.z; As[qv*4+3][row] = v.w;
        }
        #pragma unroll
        for (int i = 0; i < 2; i++) {   // B tile: coalesced rows of g_Wt
            int idx = t + i*256;
            int kq = idx >> 5, ev = idx & 31;
            *(float4*)&Bs[kq][ev*4] =
                *(const float4*)(g_Wt + (size_t)(kk*BK + kq)*E_ + e0 + ev*4);
        }
        __syncthreads();

        #pragma unroll
        for (int kq = 0; kq < BK; kq++) {
            float a[8], bb[8];
            *(float4*)&a[0]  = *(const float4*)&As[kq][ty*8];
            *(float4*)&a[4]  = *(const float4*)&As[kq][ty*8 + 4];
            *(float4*)&bb[0] = *(const float4*)&Bs[kq][tx*8];
            *(float4*)&bb[4] = *(const float4*)&Bs[kq][tx*8 + 4];
            #pragma unroll
            for (int i = 0; i < 8; i++)
                #pragma unroll
                for (int j = 0; j < 8; j++)
                    acc[i][j] += a[i] * bb[j];
        }
        __syncthreads();
    }

    // Epilogue: + proj_b + ctx[seg], vectorized stores (output is row-major M x 768)
    float bias[8];
    *(float4*)&bias[0] = *(const float4*)(proj_b + e0 + tx*8);
    *(float4*)&bias[4] = *(const float4*)(proj_b + e0 + tx*8 + 4);

    #pragma unroll
    for (int i = 0; i < 8; i++) {
        int mrow = ty*8 + i;
        const float* crow = g_ctx + (size_t)segrow[mrow]*E_ + e0 + tx*8;
        float4 c0 = *(const float4*)crow;
        float4 c1 = *(const float4*)(crow + 4);
        float4 o0, o1;
        o0.x = acc[i][0] + bias[0] + c0.x;
        o0.y = acc[i][1] + bias[1] + c0.y;
        o0.z = acc[i][2] + bias[2] + c0.z;
        o0.w = acc[i][3] + bias[3] + c0.w;
        o1.x = acc[i][4] + bias[4] + c1.x;
        o1.y = acc[i][5] + bias[5] + c1.y;
        o1.z = acc[i][6] + bias[6] + c1.z;
        o1.w = acc[i][7] + bias[7] + c1.w;
        float* op = out + (size_t)(m0 + mrow)*E_ + e0 + tx*8;
        *(float4*)op       = o0;
        *(float4*)(op + 4) = o1;
    }
}

// ---------------------------------------------------------------------------
extern "C" void kernel_launch(void* const* d_in, const int* in_sizes, int n_in,
                              void* d_out, int out_size) {
    const float* x      = (const float*)d_in[0];
    const int*   cidx   = (const int*)d_in[1];
    const float* proj_w = (const float*)d_in[2];
    const float* proj_b = (const float*)d_in[3];
    const float* ctx_w  = (const float*)d_in[4];
    const float* ctx_b  = (const float*)d_in[5];
    float*       out    = (float*)d_out;

    k_init<<<1, 256>>>(cidx);

    dim3 trb(32, 8);
    k_tr<<<dim3(K_/32, E_/32), trb>>>(proj_w, E_, K_, 0);   // g_Wt
    k_tr<<<dim3(E_/32, E_/32), trb>>>(ctx_w,  E_, E_, 1);   // g_CtxT

    k_xbar<<<B_*C_, 256>>>(x, cidx);
    k_ctx<<<NSEG, E_>>>(proj_b, ctx_b);

    k_gemm<<<dim3(E_/BN, M_/BM), 256>>>(x, cidx, proj_b, out);
}

// round 4
// speedup vs baseline: 1.3217x; 1.3217x over previous
#include <cuda_runtime.h>
#include <cstdint>

// Problem constants
#define B_      32
#define C_      8
#define H_      224
#define W_      224
#define E_      768
#define P_      16
#define HP_     14
#define NPATCH  196
#define NSEG    32
#define K_      256
#define M_      (B_*C_*NPATCH)  // 50176

// Static device scratch (allocation-free contract)
__device__ float g_Wt[K_*E_];
__device__ float g_CtxT[E_*E_];
__device__ float g_xsum[NSEG*K_];
__device__ float g_cnt[NSEG];
__device__ float g_ctx[NSEG*E_];

// ---------------------------------------------------------------------------
__global__ void k_init(const int* __restrict__ cidx) {
    int t = threadIdx.x;
    for (int i = t; i < NSEG*K_; i += 256) g_xsum[i] = 0.f;
    if (t < NSEG) g_cnt[t] = 0.f;
    __syncthreads();
    if (t < B_*C_) atomicAdd(&g_cnt[cidx[t] & (NSEG-1)], 1.0f);
}

__global__ void k_tr(const float* __restrict__ src, int R, int Ccols, int which) {
    __shared__ float tile[32][33];
    float* dst = (which == 0) ? g_Wt : g_CtxT;
    int r0 = blockIdx.y * 32, c0 = blockIdx.x * 32;
    int tx = threadIdx.x, ty = threadIdx.y;
    #pragma unroll
    for (int i = 0; i < 32; i += 8)
        tile[ty+i][tx] = src[(size_t)(r0+ty+i)*Ccols + c0 + tx];
    __syncthreads();
    #pragma unroll
    for (int i = 0; i < 32; i += 8)
        dst[(size_t)(c0+ty+i)*R + r0 + tx] = tile[tx][ty+i];
}

// 512 blocks: 2 per (b,c), splitting hp range
__global__ void k_xbar(const float* __restrict__ x, const int* __restrict__ cidx) {
    int bc = blockIdx.x >> 1;
    int z  = blockIdx.x & 1;
    int t = threadIdx.x;
    int p = t >> 4, q = t & 15;
    const float* base = x + (size_t)bc * H_ * W_ + p * W_ + q;
    float s = 0.f;
    for (int hp = z*7; hp < z*7 + 7; hp++)
        #pragma unroll
        for (int wp = 0; wp < HP_; wp++)
            s += base[(hp*P_)*W_ + wp*P_];
    s *= (1.0f / (float)NPATCH);
    atomicAdd(&g_xsum[(cidx[bc] & (NSEG-1))*K_ + t], s);
}

__global__ void k_ctx(const float* __restrict__ proj_b, const float* __restrict__ ctx_b) {
    int s = blockIdx.x, t = threadIdx.x;
    __shared__ float xm[K_];
    __shared__ float mu[E_];
    if (t < K_) {
        float cn = fmaxf(g_cnt[s], 1.0f);
        xm[t] = g_xsum[s*K_ + t] / cn;
    }
    __syncthreads();
    float d = 0.f;
    #pragma unroll 4
    for (int k = 0; k < K_; k++) d += xm[k] * g_Wt[k*E_ + t];
    mu[t] = d + proj_b[t];
    __syncthreads();
    float c = 0.f;
    #pragma unroll 4
    for (int f = 0; f < E_; f++) c += mu[f] * g_CtxT[f*E_ + t];
    g_ctx[s*E_ + t] = c + ctx_b[t];
}

// ---------------------------------------------------------------------------
// TF32 tensor-core GEMM via mma.sync (sm_80 path, compiles at sm_100).
// out[m,e] = patch[m,:]·proj_w[e,:] + proj_b[e] + ctx[seg(m),e]
// CTA tile 128x128, K in 8 chunks of 32. Fragment-layout SMEM staging.
#define BM 128
#define BN 128
#define NCH 8
// Per stage: A frags 4ks*8mt*4slot*32lane = 4096 u32; B frags 4ks*16nt*2slot*32 = 4096 u32
#define A_U32 4096
#define STG_U32 8192

static __device__ __forceinline__ uint32_t f2tf32(float f) {
    uint32_t r;
    asm("cvt.rna.tf32.f32 %0, %1;" : "=r"(r) : "f"(f));
    return r;
}
static __device__ __forceinline__ void mma_tf32(float* c, const uint32_t* a, const uint32_t* b) {
    asm volatile("mma.sync.aligned.m16n8k8.row.col.f32.tf32.tf32.f32 "
                 "{%0,%1,%2,%3}, {%4,%5,%6,%7}, {%8,%9}, {%0,%1,%2,%3};"
                 : "+f"(c[0]), "+f"(c[1]), "+f"(c[2]), "+f"(c[3])
                 : "r"(a[0]), "r"(a[1]), "r"(a[2]), "r"(a[3]), "r"(b[0]), "r"(b[1]));
}

__global__ __launch_bounds__(256)
void k_gemm_mma(const float* __restrict__ x, const int* __restrict__ cidx,
                const float* __restrict__ proj_w, const float* __restrict__ proj_b,
                float* __restrict__ out) {
    extern __shared__ uint32_t dsm[];   // 2 stages x 8192 u32 = 64 KB
    __shared__ int rowoff[BM];
    __shared__ int segrow[BM];

    int t = threadIdx.x;
    int lane = t & 31;
    int wid = t >> 5;
    int wm = wid >> 1;       // 0..3  (M direction, 32 rows each)
    int wn = wid & 1;        // 0..1  (N direction, 64 cols each)
    int m0 = blockIdx.y * BM;
    int e0 = blockIdx.x * BN;

    if (t < BM) {
        int m  = m0 + t;
        int b  = m / (C_ * NPATCH);
        int n  = m - b * (C_ * NPATCH);
        int c  = n / NPATCH;
        int r  = n - c * NPATCH;
        int hp = r / HP_;
        int wp = r - hp * HP_;
        rowoff[t] = ((b * C_ + c) * H_ + hp * P_) * W_ + wp * P_;
        segrow[t] = cidx[m / NPATCH] & (NSEG-1);
    }
    __syncthreads();

    float acc[2][8][4];
    #pragma unroll
    for (int i = 0; i < 2; i++)
        #pragma unroll
        for (int j = 0; j < 8; j++)
            #pragma unroll
            for (int s = 0; s < 4; s++) acc[i][j][s] = 0.f;

    // Precompute per-thread staging indices. idx = t + 256*j, row = idx>>3, g = idx&7.
    // A value (row, kk=g*4): frag slot = ((g&1)<<1)|((row&15)>>3), ks = g>>1,
    //   mtile = row>>4, lane base = (row&7)*4  [wait: gid = (row&15)&7]
    // B value (n=row, kk=g*4): ks = g>>1, slot = g&1, ntile = row>>3, lane base = (row&7)*4.
    int sAi[4], sBi[4], gAo[4];
    const float* gB[4];
    #pragma unroll
    for (int j = 0; j < 4; j++) {
        int idx = t + 256 * j;
        int row = idx >> 3, g = idx & 7;
        int rA = row & 15;
        int slotA = ((g & 1) << 1) | (rA >> 3);
        sAi[j] = (((g >> 1) * 8 + (row >> 4)) * 4 + slotA) * 32 + (rA & 7) * 4;
        sBi[j] = (((g >> 1) * 16 + (row >> 3)) * 2 + (g & 1)) * 32 + (row & 7) * 4;
        gAo[j] = rowoff[row] + (g >> 2) * W_ + (g & 3) * 4;   // + c*2*W_ per chunk
        gB[j]  = proj_w + (size_t)(e0 + row) * K_ + g * 4;    // + c*32 per chunk
    }

    float4 ra[4], rb[4];
    #pragma unroll
    for (int j = 0; j < 4; j++) {
        ra[j] = *(const float4*)(x + gAo[j]);
        rb[j] = *(const float4*)(gB[j]);
    }

    for (int c = 0; c < NCH; c++) {
        uint32_t* SA = dsm + (c & 1) * STG_U32;
        uint32_t* SB = SA + A_U32;
        // Stage with RNA tf32 rounding
        #pragma unroll
        for (int j = 0; j < 4; j++) {
            uint4 va = { f2tf32(ra[j].x), f2tf32(ra[j].y), f2tf32(ra[j].z), f2tf32(ra[j].w) };
            *(uint4*)&SA[sAi[j]] = va;
            uint4 vb = { f2tf32(rb[j].x), f2tf32(rb[j].y), f2tf32(rb[j].z), f2tf32(rb[j].w) };
            *(uint4*)&SB[sBi[j]] = vb;
        }
        // Prefetch next chunk while this one computes
        if (c < NCH - 1) {
            #pragma unroll
            for (int j = 0; j < 4; j++) {
                ra[j] = *(const float4*)(x + gAo[j] + (c + 1) * 2 * W_);
                rb[j] = *(const float4*)(gB[j] + (c + 1) * 32);
            }
        }
        __syncthreads();

        #pragma unroll
        for (int ks = 0; ks < 4; ks++) {
            uint32_t a[2][4], b[8][2];
            #pragma unroll
            for (int i = 0; i < 2; i++) {
                int base = ((ks * 8 + wm * 2 + i) * 4) * 32 + lane;
                a[i][0] = SA[base]; a[i][1] = SA[base + 32];
                a[i][2] = SA[base + 64]; a[i][3] = SA[base + 96];
            }
            #pragma unroll
            for (int j = 0; j < 8; j++) {
                int base = ((ks * 16 + wn * 8 + j) * 2) * 32 + lane;
                b[j][0] = SB[base]; b[j][1] = SB[base + 32];
            }
            #pragma unroll
            for (int i = 0; i < 2; i++)
                #pragma unroll
                for (int j = 0; j < 8; j++)
                    mma_tf32(acc[i][j], a[i], b[j]);
        }
        __syncthreads();
    }

    // Epilogue: c0,c1 at (gid, 2*tid..+1); c2,c3 at (gid+8, same cols)
    int gid = lane >> 2, tid = lane & 3;
    #pragma unroll
    for (int i = 0; i < 2; i++) {
        #pragma unroll
        for (int h = 0; h < 2; h++) {
            int mloc = wm * 32 + i * 16 + h * 8 + gid;
            const float* cr = g_ctx + (size_t)segrow[mloc] * E_;
            float* orow = out + (size_t)(m0 + mloc) * E_;
            #pragma unroll
            for (int j = 0; j < 8; j++) {
                int col = e0 + wn * 64 + j * 8 + tid * 2;
                float2 bv = *(const float2*)(proj_b + col);
                float2 cv = *(const float2*)(cr + col);
                float2 o;
                o.x = acc[i][j][h*2+0] + bv.x + cv.x;
                o.y = acc[i][j][h*2+1] + bv.y + cv.y;
                *(float2*)(orow + col) = o;
            }
        }
    }
}

// ---------------------------------------------------------------------------
extern "C" void kernel_launch(void* const* d_in, const int* in_sizes, int n_in,
                              void* d_out, int out_size) {
    const float* x      = (const float*)d_in[0];
    const int*   cidx   = (const int*)d_in[1];
    const float* proj_w = (const float*)d_in[2];
    const float* proj_b = (const float*)d_in[3];
    const float* ctx_w  = (const float*)d_in[4];
    const float* ctx_b  = (const float*)d_in[5];
    float*       out    = (float*)d_out;

    k_init<<<1, 256>>>(cidx);

    dim3 trb(32, 8);
    k_tr<<<dim3(K_/32, E_/32), trb>>>(proj_w, E_, K_, 0);
    k_tr<<<dim3(E_/32, E_/32), trb>>>(ctx_w,  E_, E_, 1);

    k_xbar<<<2*B_*C_, 256>>>(x, cidx);
    k_ctx<<<NSEG, E_>>>(proj_b, ctx_b);

    cudaFuncSetAttribute(k_gemm_mma, cudaFuncAttributeMaxDynamicSharedMemorySize,
                         2 * STG_U32 * 4);
    k_gemm_mma<<<dim3(E_/BN, M_/BM), 256, 2 * STG_U32 * 4>>>(x, cidx, proj_w, proj_b, out);
}

// round 5
// speedup vs baseline: 1.5026x; 1.1369x over previous
#include <cuda_runtime.h>
#include <cstdint>

// Problem constants
#define B_      32
#define C_      8
#define H_      224
#define W_      224
#define E_      768
#define P_      16
#define HP_     14
#define NPATCH  196
#define NSEG    32
#define K_      256
#define M_      (B_*C_*NPATCH)  // 50176

// Static device scratch (allocation-free contract)
__device__ float g_Wt[K_*E_];       // proj_w^T [k][e]
__device__ float g_CtxT[E_*E_];     // ctx_w^T  [f][e]
__device__ float g_Bw[E_*K_];       // proj_w rounded to tf32 (rna)
__device__ float g_xsum[NSEG*K_];
__device__ float g_cnt[NSEG];
__device__ float g_mu[NSEG*E_];
__device__ float g_ctx[NSEG*E_];

// ---------------------------------------------------------------------------
static __device__ __forceinline__ uint32_t smem_u32(const void* p) {
    uint32_t a;
    asm("{ .reg .u64 t; cvta.to.shared.u64 t, %1; cvt.u32.u64 %0, t; }" : "=r"(a) : "l"(p));
    return a;
}
static __device__ __forceinline__ uint32_t f2tf32(float f) {
    uint32_t r;
    asm("cvt.rna.tf32.f32 %0, %1;" : "=r"(r) : "f"(f));
    return r;
}
static __device__ __forceinline__ uint32_t lds32(uint32_t a) {
    uint32_t v;
    asm volatile("ld.shared.b32 %0, [%1];" : "=r"(v) : "r"(a));
    return v;
}
static __device__ __forceinline__ void cpa16(uint32_t dst, const void* src) {
    asm volatile("cp.async.cg.shared.global [%0], [%1], 16;" :: "r"(dst), "l"(src));
}
static __device__ __forceinline__ void cp_commit() {
    asm volatile("cp.async.commit_group;" ::: "memory");
}
static __device__ __forceinline__ void cp_wait2() {
    asm volatile("cp.async.wait_group 2;" ::: "memory");
}
static __device__ __forceinline__ void mma_tf32(float* c, const uint32_t* a, const uint32_t* b) {
    asm volatile("mma.sync.aligned.m16n8k8.row.col.f32.tf32.tf32.f32 "
                 "{%0,%1,%2,%3}, {%4,%5,%6,%7}, {%8,%9}, {%0,%1,%2,%3};"
                 : "+f"(c[0]), "+f"(c[1]), "+f"(c[2]), "+f"(c[3])
                 : "r"(a[0]), "r"(a[1]), "r"(a[2]), "r"(a[3]), "r"(b[0]), "r"(b[1]));
}

// ---------------------------------------------------------------------------
__global__ void k_init(const int* __restrict__ cidx) {
    int t = threadIdx.x;
    for (int i = t; i < NSEG*K_; i += 256) g_xsum[i] = 0.f;
    if (t < NSEG) g_cnt[t] = 0.f;
    __syncthreads();
    if (t < B_*C_) atomicAdd(&g_cnt[cidx[t] & (NSEG-1)], 1.0f);
}

// Round proj_w to tf32 (rna) once; halves the tf32 rounding error of the GEMM.
__global__ void k_prep(const float* __restrict__ proj_w) {
    int i = blockIdx.x * 1024 + threadIdx.x * 4;
    float4 v = *(const float4*)(proj_w + i);
    uint4 o = { f2tf32(v.x), f2tf32(v.y), f2tf32(v.z), f2tf32(v.w) };
    *(uint4*)((uint32_t*)g_Bw + i) = o;
}

__global__ void k_tr(const float* __restrict__ src, int R, int Ccols, int which) {
    __shared__ float tile[32][33];
    float* dst = (which == 0) ? g_Wt : g_CtxT;
    int r0 = blockIdx.y * 32, c0 = blockIdx.x * 32;
    int tx = threadIdx.x, ty = threadIdx.y;
    #pragma unroll
    for (int i = 0; i < 32; i += 8)
        tile[ty+i][tx] = src[(size_t)(r0+ty+i)*Ccols + c0 + tx];
    __syncthreads();
    #pragma unroll
    for (int i = 0; i < 32; i += 8)
        dst[(size_t)(c0+ty+i)*R + r0 + tx] = tile[tx][ty+i];
}

__global__ void k_xbar(const float* __restrict__ x, const int* __restrict__ cidx) {
    int bc = blockIdx.x >> 1;
    int z  = blockIdx.x & 1;
    int t = threadIdx.x;
    int p = t >> 4, q = t & 15;
    const float* base = x + (size_t)bc * H_ * W_ + p * W_ + q;
    float s = 0.f;
    for (int hp = z*7; hp < z*7 + 7; hp++)
        #pragma unroll
        for (int wp = 0; wp < HP_; wp++)
            s += base[(hp*P_)*W_ + wp*P_];
    s *= (1.0f / (float)NPATCH);
    atomicAdd(&g_xsum[(cidx[bc] & (NSEG-1))*K_ + t], s);
}

// means[s,e] for e-block of 128 cols; grid 6 x 256 threads
__global__ void k_mu(const float* __restrict__ proj_b) {
    __shared__ float xm[NSEG][K_];
    int t = threadIdx.x;
    for (int i = t; i < NSEG*K_; i += 256) {
        int s = i >> 8;
        xm[s][i & 255] = g_xsum[i] / fmaxf(g_cnt[s], 1.f);
    }
    __syncthreads();
    int e = blockIdx.x * 128 + (t & 127);
    int s0 = (t >> 7) * 16;
    float acc[16];
    #pragma unroll
    for (int s = 0; s < 16; s++) acc[s] = 0.f;
    for (int k = 0; k < K_; k++) {
        float w = g_Wt[k*E_ + e];
        #pragma unroll
        for (int s = 0; s < 16; s++) acc[s] += xm[s0+s][k] * w;
    }
    float pb = proj_b[e];
    #pragma unroll
    for (int s = 0; s < 16; s++) g_mu[(s0+s)*E_ + e] = acc[s] + pb;
}

// ctx[s,e] = mu[s,:]@ctx_w[e,:] + ctx_b[e]; grid 6 x 256, 96KB smem
__global__ void k_ctx2(const float* __restrict__ ctx_b) {
    extern __shared__ float mus[];   // [32][768]
    int t = threadIdx.x;
    for (int i = t; i < NSEG*E_; i += 256) mus[i] = g_mu[i];
    __syncthreads();
    int e = blockIdx.x * 128 + (t & 127);
    int s0 = (t >> 7) * 16;
    float acc[16];
    #pragma unroll
    for (int s = 0; s < 16; s++) acc[s] = 0.f;
    for (int f = 0; f < E_; f++) {
        float w = g_CtxT[f*E_ + e];
        #pragma unroll
        for (int s = 0; s < 16; s++) acc[s] += mus[(s0+s)*E_ + f] * w;
    }
    float cb = ctx_b[e];
    #pragma unroll
    for (int s = 0; s < 16; s++) g_ctx[(s0+s)*E_ + e] = acc[s] + cb;
}

// ---------------------------------------------------------------------------
// TF32 mma.sync GEMM, cp.async 3-stage pipeline, 2 CTAs/SM.
// SMEM per stage: A 128x32 f32 (16KB, XOR-swizzled cols) + B same = 32KB.
#define BM 128
#define BN 128
#define NCH 8
#define STG_B 32768
#define NSTG 3

__global__ __launch_bounds__(256, 2)
void k_gemm_mma(const float* __restrict__ x, const int* __restrict__ cidx,
                const float* __restrict__ proj_b, float* __restrict__ out) {
    extern __shared__ char dsm[];
    __shared__ int rowoff[BM];
    __shared__ int segrow[BM];

    int t = threadIdx.x;
    int lane = t & 31;
    int wid = t >> 5;
    int wm = wid >> 1, wn = wid & 1;
    int m0 = blockIdx.y * BM;
    int e0 = blockIdx.x * BN;
    uint32_t base_u = smem_u32(dsm);

    if (t < BM) {
        int m  = m0 + t;
        int b  = m / (C_ * NPATCH);
        int n  = m - b * (C_ * NPATCH);
        int c  = n / NPATCH;
        int r  = n - c * NPATCH;
        int hp = r / HP_;
        int wp = r - hp * HP_;
        rowoff[t] = ((b * C_ + c) * H_ + hp * P_) * W_ + wp * P_;
        segrow[t] = cidx[m / NPATCH] & (NSEG-1);
    }
    __syncthreads();

    // Copy-descriptor components (derived from t; only A src ptrs kept)
    int g4  = t & 7;                      // 16B-granule within 128B row
    int rr  = t >> 3;                     // base row (rows rr, rr+32, rr+64, rr+96)
    uint32_t sw = (uint32_t)((g4 ^ (rr & 7)) << 4);
    const float* srcA[4];
    #pragma unroll
    for (int j = 0; j < 4; j++)
        srcA[j] = x + rowoff[rr + 32*j] + (g4 >> 2) * W_ + (g4 & 3) * 4;
    const float* srcB0 = g_Bw + (size_t)(e0 + rr) * K_ + g4 * 4;
    uint32_t dstA0 = base_u + rr * 128 + sw;

    // Issue one stage (chunk c -> slot st)
    auto issue = [&](int c, int st) {
        uint32_t da = dstA0 + st * STG_B;
        int offA = c * 2 * W_;
        int offB = c * 32;
        #pragma unroll
        for (int j = 0; j < 4; j++)
            cpa16(da + j * 4096, srcA[j] + offA);
        #pragma unroll
        for (int j = 0; j < 4; j++)
            cpa16(da + 16384 + j * 4096, srcB0 + (size_t)j * 32 * K_ + offB);
    };

    issue(0, 0); cp_commit();
    issue(1, 1); cp_commit();
    issue(2, 2); cp_commit();

    float acc[2][8][4];
    #pragma unroll
    for (int i = 0; i < 2; i++)
        #pragma unroll
        for (int j = 0; j < 8; j++)
            #pragma unroll
            for (int s = 0; s < 4; s++) acc[i][j][s] = 0.f;

    int gid = lane >> 2, tid = lane & 3;

    for (int c = 0; c < NCH; c++) {
        int st = c % NSTG;
        cp_wait2();
        __syncthreads();

        uint32_t sa = base_u + st * STG_B;
        uint32_t sb = sa + 16384;
        #pragma unroll
        for (int ks = 0; ks < 4; ks++) {
            uint32_t a[2][4], b[8][2];
            #pragma unroll
            for (int i = 0; i < 2; i++) {
                #pragma unroll
                for (int s = 0; s < 4; s++) {
                    int r = wm * 32 + i * 16 + (s & 1) * 8 + gid;
                    int k4 = ks * 2 + (s >> 1);
                    a[i][s] = lds32(sa + r * 128 + ((k4 ^ (r & 7)) << 4) + tid * 4);
                }
            }
            #pragma unroll
            for (int j = 0; j < 8; j++) {
                #pragma unroll
                for (int s = 0; s < 2; s++) {
                    int n = wn * 64 + j * 8 + gid;
                    int k4 = ks * 2 + s;
                    b[j][s] = lds32(sb + n * 128 + ((k4 ^ (n & 7)) << 4) + tid * 4);
                }
            }
            #pragma unroll
            for (int i = 0; i < 2; i++)
                #pragma unroll
                for (int j = 0; j < 8; j++)
                    mma_tf32(acc[i][j], a[i], b[j]);
        }
        __syncthreads();
        if (c + 3 < NCH) issue(c + 3, st);
        cp_commit();   // empty group when no issue: keeps wait_group arithmetic uniform
    }

    // Epilogue: c0,c1 at (gid, 2*tid..+1); c2,c3 at (gid+8, same cols)
    #pragma unroll
    for (int i = 0; i < 2; i++) {
        #pragma unroll
        for (int h = 0; h < 2; h++) {
            int mloc = wm * 32 + i * 16 + h * 8 + gid;
            const float* cr = g_ctx + (size_t)segrow[mloc] * E_;
            float* orow = out + (size_t)(m0 + mloc) * E_;
            #pragma unroll
            for (int j = 0; j < 8; j++) {
                int col = e0 + wn * 64 + j * 8 + tid * 2;
                float2 bv = *(const float2*)(proj_b + col);
                float2 cv = *(const float2*)(cr + col);
                float2 o;
                o.x = acc[i][j][h*2+0] + bv.x + cv.x;
                o.y = acc[i][j][h*2+1] + bv.y + cv.y;
                *(float2*)(orow + col) = o;
            }
        }
    }
}

// ---------------------------------------------------------------------------
extern "C" void kernel_launch(void* const* d_in, const int* in_sizes, int n_in,
                              void* d_out, int out_size) {
    const float* x      = (const float*)d_in[0];
    const int*   cidx   = (const int*)d_in[1];
    const float* proj_w = (const float*)d_in[2];
    const float* proj_b = (const float*)d_in[3];
    const float* ctx_w  = (const float*)d_in[4];
    const float* ctx_b  = (const float*)d_in[5];
    float*       out    = (float*)d_out;

    k_init<<<1, 256>>>(cidx);
    k_prep<<<E_*K_/1024, 256>>>(proj_w);

    dim3 trb(32, 8);
    k_tr<<<dim3(K_/32, E_/32), trb>>>(proj_w, E_, K_, 0);
    k_tr<<<dim3(E_/32, E_/32), trb>>>(ctx_w,  E_, E_, 1);

    k_xbar<<<2*B_*C_, 256>>>(x, cidx);
    k_mu<<<E_/128, 256>>>(proj_b);
    cudaFuncSetAttribute(k_ctx2, cudaFuncAttributeMaxDynamicSharedMemorySize, NSEG*E_*4);
    k_ctx2<<<E_/128, 256, NSEG*E_*4>>>(ctx_b);

    cudaFuncSetAttribute(k_gemm_mma, cudaFuncAttributeMaxDynamicSharedMemorySize, NSTG*STG_B);
    k_gemm_mma<<<dim3(E_/BN, M_/BM), 256, NSTG*STG_B>>>(x, cidx, proj_b, out);
}

// round 6
// speedup vs baseline: 1.5676x; 1.0432x over previous
#include <cuda_runtime.h>
#include <cuda_fp16.h>
#include <cstdint>

// Problem constants
#define B_      32
#define C_      8
#define H_      224
#define W_      224
#define E_      768
#define P_      16
#define HP_     14
#define NPATCH  196
#define NSEG    32
#define K_      256
#define M_      (B_*C_*NPATCH)  // 50176

// Static device scratch (allocation-free contract)
__device__ __half g_xh[B_*C_*H_*W_];   // x converted to half (25.7 MB)
__device__ __half g_Bh[E_*K_];         // proj_w converted to half
__device__ float g_Wt[K_*E_];          // proj_w^T [k][e] fp32 (ctx path)
__device__ float g_CtxT[E_*E_];        // ctx_w^T  [f][e]
__device__ float g_xsum[NSEG*K_];
__device__ float g_cnt[NSEG];
__device__ float g_mu[NSEG*E_];
__device__ float g_ctx[NSEG*E_];

// ---------------------------------------------------------------------------
static __device__ __forceinline__ uint32_t smem_u32(const void* p) {
    uint32_t a;
    asm("{ .reg .u64 t; cvta.to.shared.u64 t, %1; cvt.u32.u64 %0, t; }" : "=r"(a) : "l"(p));
    return a;
}
static __device__ __forceinline__ void cpa16(uint32_t dst, const void* src) {
    asm volatile("cp.async.cg.shared.global [%0], [%1], 16;" :: "r"(dst), "l"(src));
}
static __device__ __forceinline__ void cp_commit() {
    asm volatile("cp.async.commit_group;" ::: "memory");
}
static __device__ __forceinline__ void cp_wait2() {
    asm volatile("cp.async.wait_group 2;" ::: "memory");
}
static __device__ __forceinline__ void ldmx4(uint32_t* r, uint32_t a) {
    asm volatile("ldmatrix.sync.aligned.m8n8.x4.shared.b16 {%0,%1,%2,%3}, [%4];"
                 : "=r"(r[0]), "=r"(r[1]), "=r"(r[2]), "=r"(r[3]) : "r"(a));
}
static __device__ __forceinline__ void mma_f16(float* c, const uint32_t* a, const uint32_t* b) {
    asm volatile("mma.sync.aligned.m16n8k16.row.col.f32.f16.f16.f32 "
                 "{%0,%1,%2,%3}, {%4,%5,%6,%7}, {%8,%9}, {%0,%1,%2,%3};"
                 : "+f"(c[0]), "+f"(c[1]), "+f"(c[2]), "+f"(c[3])
                 : "r"(a[0]), "r"(a[1]), "r"(a[2]), "r"(a[3]), "r"(b[0]), "r"(b[1]));
}

// ---------------------------------------------------------------------------
__global__ void k_init(const int* __restrict__ cidx) {
    int t = threadIdx.x;
    for (int i = t; i < NSEG*K_; i += 256) g_xsum[i] = 0.f;
    if (t < NSEG) g_cnt[t] = 0.f;
    __syncthreads();
    if (t < B_*C_) atomicAdd(&g_cnt[cidx[t] & (NSEG-1)], 1.0f);
}

// Convert a float buffer to half (8 elems/thread)
__global__ void k_tohalf(const float* __restrict__ src, __half* __restrict__ dst) {
    size_t i = ((size_t)blockIdx.x * 256 + threadIdx.x) * 8;
    float4 v0 = *(const float4*)(src + i);
    float4 v1 = *(const float4*)(src + i + 4);
    __half2 h[4];
    h[0] = __floats2half2_rn(v0.x, v0.y);
    h[1] = __floats2half2_rn(v0.z, v0.w);
    h[2] = __floats2half2_rn(v1.x, v1.y);
    h[3] = __floats2half2_rn(v1.z, v1.w);
    *(uint4*)(dst + i) = *(uint4*)h;
}

__global__ void k_tr(const float* __restrict__ src, int R, int Ccols, int which) {
    __shared__ float tile[32][33];
    float* dst = (which == 0) ? g_Wt : g_CtxT;
    int r0 = blockIdx.y * 32, c0 = blockIdx.x * 32;
    int tx = threadIdx.x, ty = threadIdx.y;
    #pragma unroll
    for (int i = 0; i < 32; i += 8)
        tile[ty+i][tx] = src[(size_t)(r0+ty+i)*Ccols + c0 + tx];
    __syncthreads();
    #pragma unroll
    for (int i = 0; i < 32; i += 8)
        dst[(size_t)(c0+ty+i)*R + r0 + tx] = tile[tx][ty+i];
}

__global__ void k_xbar(const float* __restrict__ x, const int* __restrict__ cidx) {
    int bc = blockIdx.x >> 1;
    int z  = blockIdx.x & 1;
    int t = threadIdx.x;
    int p = t >> 4, q = t & 15;
    const float* base = x + (size_t)bc * H_ * W_ + p * W_ + q;
    float s = 0.f;
    for (int hp = z*7; hp < z*7 + 7; hp++)
        #pragma unroll
        for (int wp = 0; wp < HP_; wp++)
            s += base[(hp*P_)*W_ + wp*P_];
    s *= (1.0f / (float)NPATCH);
    atomicAdd(&g_xsum[(cidx[bc] & (NSEG-1))*K_ + t], s);
}

__global__ void k_mu(const float* __restrict__ proj_b) {
    __shared__ float xm[NSEG][K_];
    int t = threadIdx.x;
    for (int i = t; i < NSEG*K_; i += 256) {
        int s = i >> 8;
        xm[s][i & 255] = g_xsum[i] / fmaxf(g_cnt[s], 1.f);
    }
    __syncthreads();
    int e = blockIdx.x * 128 + (t & 127);
    int s0 = (t >> 7) * 16;
    float acc[16];
    #pragma unroll
    for (int s = 0; s < 16; s++) acc[s] = 0.f;
    for (int k = 0; k < K_; k++) {
        float w = g_Wt[k*E_ + e];
        #pragma unroll
        for (int s = 0; s < 16; s++) acc[s] += xm[s0+s][k] * w;
    }
    float pb = proj_b[e];
    #pragma unroll
    for (int s = 0; s < 16; s++) g_mu[(s0+s)*E_ + e] = acc[s] + pb;
}

__global__ void k_ctx2(const float* __restrict__ ctx_b) {
    extern __shared__ float mus[];   // [32][768]
    int t = threadIdx.x;
    for (int i = t; i < NSEG*E_; i += 256) mus[i] = g_mu[i];
    __syncthreads();
    int e = blockIdx.x * 128 + (t & 127);
    int s0 = (t >> 7) * 16;
    float acc[16];
    #pragma unroll
    for (int s = 0; s < 16; s++) acc[s] = 0.f;
    for (int f = 0; f < E_; f++) {
        float w = g_CtxT[f*E_ + e];
        #pragma unroll
        for (int s = 0; s < 16; s++) acc[s] += mus[(s0+s)*E_ + f] * w;
    }
    float cb = ctx_b[e];
    #pragma unroll
    for (int s = 0; s < 16; s++) g_ctx[(s0+s)*E_ + e] = acc[s] + cb;
}

// ---------------------------------------------------------------------------
// FP16 mma.sync GEMM, cp.async 3-stage pipeline, ldmatrix fragment loads.
// SMEM stage: A 128 rows x 80B (32 halves + pad) + B same = 20480 B.
#define BM 128
#define BN 128
#define NCH 8
#define ROWB 80
#define A_BYTES (BM*ROWB)     // 10240
#define STG_B (2*A_BYTES)     // 20480
#define NSTG 3

__global__ __launch_bounds__(256, 2)
void k_gemm_mma(const int* __restrict__ cidx, const float* __restrict__ proj_b,
                float* __restrict__ out) {
    extern __shared__ char dsm[];
    __shared__ int rowoff[BM];
    __shared__ int segrow[BM];

    int t = threadIdx.x;
    int lane = t & 31;
    int wid = t >> 5;
    int wm = wid >> 1, wn = wid & 1;
    int m0 = blockIdx.y * BM;
    int e0 = blockIdx.x * BN;
    uint32_t base_u = smem_u32(dsm);

    if (t < BM) {
        int m  = m0 + t;
        int b  = m / (C_ * NPATCH);
        int n  = m - b * (C_ * NPATCH);
        int c  = n / NPATCH;
        int r  = n - c * NPATCH;
        int hp = r / HP_;
        int wp = r - hp * HP_;
        rowoff[t] = ((b * C_ + c) * H_ + hp * P_) * W_ + wp * P_;
        segrow[t] = cidx[m / NPATCH] & (NSEG-1);
    }
    __syncthreads();

    // Per-thread copy descriptors: idx = t, t+256; row = idx>>2, seg = idx&3
    const __half* srcA[2];
    const __half* srcB[2];
    uint32_t dstOff[2];
    #pragma unroll
    for (int j = 0; j < 2; j++) {
        int idx = t + 256 * j;
        int row = idx >> 2, seg = idx & 3;
        srcA[j] = g_xh + rowoff[row] + (seg >> 1) * W_ + (seg & 1) * 8;  // + c*2*W_
        srcB[j] = g_Bh + (size_t)(e0 + row) * K_ + seg * 8;             // + c*32
        dstOff[j] = row * ROWB + seg * 16;
    }

    auto issue = [&](int c, int st) {
        uint32_t sb = base_u + st * STG_B;
        #pragma unroll
        for (int j = 0; j < 2; j++) {
            cpa16(sb + dstOff[j], srcA[j] + c * 2 * W_);
            cpa16(sb + A_BYTES + dstOff[j], srcB[j] + c * 32);
        }
    };

    issue(0, 0); cp_commit();
    issue(1, 1); cp_commit();
    issue(2, 2); cp_commit();

    float acc[2][8][4];
    #pragma unroll
    for (int i = 0; i < 2; i++)
        #pragma unroll
        for (int j = 0; j < 8; j++)
            #pragma unroll
            for (int s = 0; s < 4; s++) acc[i][j][s] = 0.f;

    int gid = lane >> 2, tid = lane & 3;

    for (int c = 0; c < NCH; c++) {
        int st = c % NSTG;
        cp_wait2();
        __syncthreads();

        uint32_t sa = base_u + st * STG_B;
        uint32_t sb = sa + A_BYTES;
        #pragma unroll
        for (int ks = 0; ks < 2; ks++) {
            // A: 2 ldmatrix.x4, each m16 x k16
            uint32_t a[2][4];
            #pragma unroll
            for (int i = 0; i < 2; i++) {
                int r = wm * 32 + i * 16 + (lane & 15);
                int g = ks * 2 + (lane >> 4);
                ldmx4(a[i], sa + r * ROWB + g * 16);
            }
            // B: 4 ldmatrix.x4, each covers 2 n-tiles x k16
            uint32_t b[8][2];
            #pragma unroll
            for (int j = 0; j < 4; j++) {
                int nt = 2 * j + ((lane >> 4) & 1);
                int n = wn * 64 + nt * 8 + (lane & 7);
                int g = ks * 2 + ((lane >> 3) & 1);
                uint32_t r4[4];
                ldmx4(r4, sb + n * ROWB + g * 16);
                b[2*j][0] = r4[0]; b[2*j][1] = r4[1];
                b[2*j+1][0] = r4[2]; b[2*j+1][1] = r4[3];
            }
            #pragma unroll
            for (int i = 0; i < 2; i++)
                #pragma unroll
                for (int j = 0; j < 8; j++)
                    mma_f16(acc[i][j], a[i], b[j]);
        }
        __syncthreads();
        if (c + 3 < NCH) issue(c + 3, st);
        cp_commit();
    }

    // Epilogue (same acc layout as tf32 m16n8k8 pair): c0,c1 @ row gid; c2,c3 @ gid+8
    #pragma unroll
    for (int i = 0; i < 2; i++) {
        #pragma unroll
        for (int h = 0; h < 2; h++) {
            int mloc = wm * 32 + i * 16 + h * 8 + gid;
            const float* cr = g_ctx + (size_t)segrow[mloc] * E_;
            float* orow = out + (size_t)(m0 + mloc) * E_;
            #pragma unroll
            for (int j = 0; j < 8; j++) {
                int col = e0 + wn * 64 + j * 8 + tid * 2;
                float2 bv = *(const float2*)(proj_b + col);
                float2 cv = *(const float2*)(cr + col);
                float2 o;
                o.x = acc[i][j][h*2+0] + bv.x + cv.x;
                o.y = acc[i][j][h*2+1] + bv.y + cv.y;
                *(float2*)(orow + col) = o;
            }
        }
    }
}

// ---------------------------------------------------------------------------
extern "C" void kernel_launch(void* const* d_in, const int* in_sizes, int n_in,
                              void* d_out, int out_size) {
    const float* x      = (const float*)d_in[0];
    const int*   cidx   = (const int*)d_in[1];
    const float* proj_w = (const float*)d_in[2];
    const float* proj_b = (const float*)d_in[3];
    const float* ctx_w  = (const float*)d_in[4];
    const float* ctx_b  = (const float*)d_in[5];
    float*       out    = (float*)d_out;

    k_init<<<1, 256>>>(cidx);

    __half* xh; cudaGetSymbolAddress((void**)&xh, g_xh);
    __half* bh; cudaGetSymbolAddress((void**)&bh, g_Bh);
    k_tohalf<<<(B_*C_*H_*W_)/(256*8), 256>>>(x, xh);
    k_tohalf<<<(E_*K_)/(256*8), 256>>>(proj_w, bh);

    dim3 trb(32, 8);
    k_tr<<<dim3(K_/32, E_/32), trb>>>(proj_w, E_, K_, 0);
    k_tr<<<dim3(E_/32, E_/32), trb>>>(ctx_w,  E_, E_, 1);

    k_xbar<<<2*B_*C_, 256>>>(x, cidx);
    k_mu<<<E_/128, 256>>>(proj_b);
    cudaFuncSetAttribute(k_ctx2, cudaFuncAttributeMaxDynamicSharedMemorySize, NSEG*E_*4);
    k_ctx2<<<E_/128, 256, NSEG*E_*4>>>(ctx_b);

    cudaFuncSetAttribute(k_gemm_mma, cudaFuncAttributeMaxDynamicSharedMemorySize, NSTG*STG_B);
    k_gemm_mma<<<dim3(E_/BN, M_/BM), 256, NSTG*STG_B>>>(cidx, proj_b, out);
}

// round 8
// speedup vs baseline: 2.1802x; 1.3908x over previous
#include <cuda_runtime.h>
#include <cuda_fp16.h>
#include <cstdint>

// Problem constants
#define B_      32
#define C_      8
#define H_      224
#define W_      224
#define E_      768
#define P_      16
#define HP_     14
#define NPATCH  196
#define NSEG    32
#define K_      256
#define M_      (B_*C_*NPATCH)  // 50176

// Static device scratch
__device__ __half g_xh[B_*C_*H_*W_];   // x as half
__device__ __half g_Bh[E_*K_];         // proj_w as half
__device__ float g_part[512*K_];       // per-(bc,half) partial pixel sums
__device__ float g_mu[NSEG*E_];        // segment-mean embeddings (+proj_b)
__device__ float g_ctx[NSEG*E_];       // context vectors

// ---------------------------------------------------------------------------
static __device__ __forceinline__ uint32_t smem_u32(const void* p) {
    uint32_t a;
    asm("{ .reg .u64 t; cvta.to.shared.u64 t, %1; cvt.u32.u64 %0, t; }" : "=r"(a) : "l"(p));
    return a;
}
static __device__ __forceinline__ void cpa16(uint32_t dst, const void* src) {
    asm volatile("cp.async.cg.shared.global [%0], [%1], 16;" :: "r"(dst), "l"(src));
}
static __device__ __forceinline__ void cp_commit() {
    asm volatile("cp.async.commit_group;" ::: "memory");
}
static __device__ __forceinline__ void cp_wait2() {
    asm volatile("cp.async.wait_group 2;" ::: "memory");
}
static __device__ __forceinline__ void ldmx4(uint32_t* r, uint32_t a) {
    asm volatile("ldmatrix.sync.aligned.m8n8.x4.shared.b16 {%0,%1,%2,%3}, [%4];"
                 : "=r"(r[0]), "=r"(r[1]), "=r"(r[2]), "=r"(r[3]) : "r"(a));
}
static __device__ __forceinline__ void mma_f16(float* c, const uint32_t* a, const uint32_t* b) {
    asm volatile("mma.sync.aligned.m16n8k16.row.col.f32.f16.f16.f32 "
                 "{%0,%1,%2,%3}, {%4,%5,%6,%7}, {%8,%9}, {%0,%1,%2,%3};"
                 : "+f"(c[0]), "+f"(c[1]), "+f"(c[2]), "+f"(c[3])
                 : "r"(a[0]), "r"(a[1]), "r"(a[2]), "r"(a[3]), "r"(b[0]), "r"(b[1]));
}

// ---------------------------------------------------------------------------
// Launch 0/1: float -> half conversion (8 elems/thread)
__global__ void k_tohalf(const float* __restrict__ src, __half* __restrict__ dst) {
    size_t i = ((size_t)blockIdx.x * 256 + threadIdx.x) * 8;
    float4 v0 = *(const float4*)(src + i);
    float4 v1 = *(const float4*)(src + i + 4);
    __half2 h[4];
    h[0] = __floats2half2_rn(v0.x, v0.y);
    h[1] = __floats2half2_rn(v0.z, v0.w);
    h[2] = __floats2half2_rn(v1.x, v1.y);
    h[3] = __floats2half2_rn(v1.z, v1.w);
    *(uint4*)(dst + i) = *(uint4*)h;
}

// Launch 2: per-(bc, half-range) pixel sums, written (not accumulated).
__global__ void k_xbar(const float* __restrict__ x) {
    int bc = blockIdx.x >> 1;
    int z  = blockIdx.x & 1;
    int t = threadIdx.x;
    int p = t >> 4, q = t & 15;
    const float* base = x + (size_t)bc * H_ * W_ + p * W_ + q;
    float s = 0.f;
    for (int hp = z*7; hp < z*7 + 7; hp++)
        #pragma unroll
        for (int wp = 0; wp < HP_; wp++)
            s += base[(hp*P_)*W_ + wp*P_];
    g_part[blockIdx.x * K_ + t] = s;
}

// Launch 3: segment counts + segment means + mu = xm@Wt + proj_b. Grid 6 x 256.
__global__ void k_mu(const int* __restrict__ cidx, const float* __restrict__ proj_w,
                     const float* __restrict__ proj_b) {
    extern __shared__ float wp[];            // [128][257]
    __shared__ float xm[NSEG*K_];            // 32 KB
    __shared__ int scnt[NSEG];
    int t = threadIdx.x;
    int e0 = blockIdx.x * 128;

    if (t < NSEG) scnt[t] = 0;
    for (int i = t; i < NSEG*K_; i += 256) xm[i] = 0.f;
    __syncthreads();
    if (t < B_*C_) atomicAdd(&scnt[cidx[t] & (NSEG-1)], 1);
    // weight panel: wp[e][k] = proj_w[e0+e][k], padded stride 257
    for (int i = t; i < 128*K_; i += 256) {
        int e = i >> 8, k = i & 255;
        wp[e*257 + k] = proj_w[(size_t)(e0+e)*K_ + k];
    }
    __syncthreads();
    // segment sums (serial over bc; all threads same seg -> conflict-free)
    for (int bc = 0; bc < B_*C_; bc++) {
        float v = g_part[(2*bc)*K_ + t] + g_part[(2*bc+1)*K_ + t];
        xm[(cidx[bc] & (NSEG-1))*K_ + t] += v;
    }
    __syncthreads();
    for (int i = t; i < NSEG*K_; i += 256) {
        int s = i >> 8;
        xm[i] *= 1.0f / ((float)NPATCH * fmaxf((float)scnt[s], 1.f));
    }
    __syncthreads();

    int e = t & 127;
    int s0 = (t >> 7) * 16;
    float acc[16];
    #pragma unroll
    for (int s = 0; s < 16; s++) acc[s] = 0.f;
    for (int k = 0; k < K_; k++) {
        float w = wp[e*257 + k];
        #pragma unroll
        for (int s = 0; s < 16; s++) acc[s] += xm[(s0+s)*K_ + k] * w;
    }
    float pb = proj_b[e0 + e];
    #pragma unroll
    for (int s = 0; s < 16; s++) g_mu[(s0+s)*E_ + e0 + e] = acc[s] + pb;
}

// Launch 4: ctx = mu @ ctx_w^T + ctx_b, transposing ctx_w tile-wise in smem. Grid 6 x 256.
__global__ void k_ctx2(const float* __restrict__ ctx_w, const float* __restrict__ ctx_b) {
    extern __shared__ float dyn[];
    float* mus = dyn;                 // [32][768]
    float* ct  = dyn + NSEG*E_;       // [128][129] transposed tile
    int t = threadIdx.x;
    int e0 = blockIdx.x * 128;

    for (int i = t; i < NSEG*E_; i += 256) mus[i] = g_mu[i];

    int e = t & 127;
    int s0 = (t >> 7) * 16;
    float acc[16];
    #pragma unroll
    for (int s = 0; s < 16; s++) acc[s] = 0.f;

    for (int f0 = 0; f0 < E_; f0 += 128) {
        __syncthreads();
        for (int i = t; i < 128*128; i += 256) {
            int er = i >> 7, fc = i & 127;
            ct[fc*129 + er] = ctx_w[(size_t)(e0+er)*E_ + f0 + fc];
        }
        __syncthreads();
        for (int f = 0; f < 128; f++) {
            float c = ct[f*129 + e];
            #pragma unroll
            for (int s = 0; s < 16; s++) acc[s] += mus[(s0+s)*E_ + f0 + f] * c;
        }
    }
    float cb = ctx_b[e0 + e];
    #pragma unroll
    for (int s = 0; s < 16; s++) g_ctx[(s0+s)*E_ + e0 + e] = acc[s] + cb;
}

// ---------------------------------------------------------------------------
// Launch 5: FP16 mma.sync GEMM. CTA 128x128, K=256 in 4 chunks of 64.
// Stage: A 128x128B + B 128x128B = 32KB; 3 stages; XOR-swizzled 16B granules.
#define BM 128
#define BN 128
#define CK 64
#define NCH 4
#define ROWB 128
#define A_BYTES (BM*ROWB)     // 16384
#define STG_B (2*A_BYTES)     // 32768
#define NSTG 3

__global__ __launch_bounds__(256, 2)
void k_gemm_mma(const int* __restrict__ cidx, const float* __restrict__ proj_b,
                float* __restrict__ out) {
    extern __shared__ char dsm[];
    __shared__ int rowoff[BM];
    __shared__ int segrow[BM];

    int t = threadIdx.x;
    int lane = t & 31;
    int wid = t >> 5;
    int wm = wid >> 1, wn = wid & 1;
    int m0 = blockIdx.y * BM;
    int e0 = blockIdx.x * BN;
    uint32_t base_u = smem_u32(dsm);

    if (t < BM) {
        int m  = m0 + t;
        int b  = m / (C_ * NPATCH);
        int n  = m - b * (C_ * NPATCH);
        int c  = n / NPATCH;
        int r  = n - c * NPATCH;
        int hp = r / HP_;
        int wp = r - hp * HP_;
        rowoff[t] = ((b * C_ + c) * H_ + hp * P_) * W_ + wp * P_;
        segrow[t] = cidx[m / NPATCH] & (NSEG-1);
    }
    __syncthreads();

    // chunk c covers local k = 0..63 : pixel rows 4c..4c+3, 16 halves each.
    auto issue = [&](int c, int st) {
        uint32_t sb = base_u + st * STG_B;
        #pragma unroll
        for (int j = 0; j < 4; j++) {
            int idx = t + 256 * j;
            int row = idx >> 3, g = idx & 7;
            uint32_t sw = (uint32_t)((g ^ (row & 7)) << 4);
            const __half* pa = g_xh + rowoff[row] + (c*4 + (g >> 1)) * W_ + (g & 1) * 8;
            cpa16(sb + row * ROWB + sw, pa);
            const __half* pb = g_Bh + (size_t)(e0 + row) * K_ + c * CK + g * 8;
            cpa16(sb + A_BYTES + row * ROWB + sw, pb);
        }
    };

    issue(0, 0); cp_commit();
    issue(1, 1); cp_commit();
    issue(2, 2); cp_commit();

    float acc[2][8][4];
    #pragma unroll
    for (int i = 0; i < 2; i++)
        #pragma unroll
        for (int j = 0; j < 8; j++)
            #pragma unroll
            for (int s = 0; s < 4; s++) acc[i][j][s] = 0.f;

    int gid = lane >> 2, tid = lane & 3;

    for (int c = 0; c < NCH; c++) {
        int st = c % NSTG;
        cp_wait2();
        __syncthreads();

        uint32_t sa = base_u + st * STG_B;
        uint32_t sbb = sa + A_BYTES;
        #pragma unroll
        for (int ks = 0; ks < 4; ks++) {
            uint32_t a[2][4];
            #pragma unroll
            for (int i = 0; i < 2; i++) {
                int r = wm * 32 + i * 16 + (lane & 15);
                int g = 2 * ks + (lane >> 4);
                ldmx4(a[i], sa + r * ROWB + ((g ^ (r & 7)) << 4));
            }
            uint32_t b[8][2];
            #pragma unroll
            for (int j = 0; j < 4; j++) {
                int nt = 2 * j + ((lane >> 4) & 1);
                int n = wn * 64 + nt * 8 + (lane & 7);
                int g = 2 * ks + ((lane >> 3) & 1);
                uint32_t r4[4];
                ldmx4(r4, sbb + n * ROWB + ((g ^ (n & 7)) << 4));
                b[2*j][0] = r4[0]; b[2*j][1] = r4[1];
                b[2*j+1][0] = r4[2]; b[2*j+1][1] = r4[3];
            }
            #pragma unroll
            for (int i = 0; i < 2; i++)
                #pragma unroll
                for (int j = 0; j < 8; j++)
                    mma_f16(acc[i][j], a[i], b[j]);
        }
        __syncthreads();
        if (c + 3 < NCH) issue(c + 3, st);
        cp_commit();   // empty groups keep wait_group arithmetic uniform (in-order retire)
    }

    // Epilogue: c0,c1 @ row gid; c2,c3 @ row gid+8; cols 2*tid
    #pragma unroll
    for (int i = 0; i < 2; i++) {
        #pragma unroll
        for (int h = 0; h < 2; h++) {
            int mloc = wm * 32 + i * 16 + h * 8 + gid;
            const float* cr = g_ctx + (size_t)segrow[mloc] * E_;
            float* orow = out + (size_t)(m0 + mloc) * E_;
            #pragma unroll
            for (int j = 0; j < 8; j++) {
                int col = e0 + wn * 64 + j * 8 + tid * 2;
                float2 bv = *(const float2*)(proj_b + col);
                float2 cv = *(const float2*)(cr + col);
                float2 o;
                o.x = acc[i][j][h*2+0] + bv.x + cv.x;
                o.y = acc[i][j][h*2+1] + bv.y + cv.y;
                *(float2*)(orow + col) = o;
            }
        }
    }
}

// ---------------------------------------------------------------------------
extern "C" void kernel_launch(void* const* d_in, const int* in_sizes, int n_in,
                              void* d_out, int out_size) {
    const float* x      = (const float*)d_in[0];
    const int*   cidx   = (const int*)d_in[1];
    const float* proj_w = (const float*)d_in[2];
    const float* proj_b = (const float*)d_in[3];
    const float* ctx_w  = (const float*)d_in[4];
    const float* ctx_b  = (const float*)d_in[5];
    float*       out    = (float*)d_out;

    __half* xh; cudaGetSymbolAddress((void**)&xh, g_xh);
    __half* bh; cudaGetSymbolAddress((void**)&bh, g_Bh);

    k_tohalf<<<(B_*C_*H_*W_)/2048, 256>>>(x, xh);          // 0
    k_tohalf<<<(E_*K_)/2048, 256>>>(proj_w, bh);           // 1
    k_xbar<<<2*B_*C_, 256>>>(x);                           // 2

    cudaFuncSetAttribute(k_mu, cudaFuncAttributeMaxDynamicSharedMemorySize, 128*257*4);
    k_mu<<<E_/128, 256, 128*257*4>>>(cidx, proj_w, proj_b);            // 3

    cudaFuncSetAttribute(k_ctx2, cudaFuncAttributeMaxDynamicSharedMemorySize,
                         (NSEG*E_ + 128*129)*4);
    k_ctx2<<<E_/128, 256, (NSEG*E_ + 128*129)*4>>>(ctx_w, ctx_b);      // 4

    cudaFuncSetAttribute(k_gemm_mma, cudaFuncAttributeMaxDynamicSharedMemorySize, NSTG*STG_B);
    k_gemm_mma<<<dim3(E_/BN, M_/BM), 256, NSTG*STG_B>>>(cidx, proj_b, out);  // 5 <- ncu target
}

// round 9
// speedup vs baseline: 2.9902x; 1.3715x over previous
#include <cuda_runtime.h>
#include <cuda_fp16.h>
#include <cstdint>

// Problem constants
#define B_      32
#define C_      8
#define H_      224
#define W_      224
#define E_      768
#define P_      16
#define HP_     14
#define NPATCH  196
#define NSEG    32
#define K_      256
#define M_      (B_*C_*NPATCH)  // 50176

// Static device scratch
__device__ __half g_xh[B_*C_*H_*W_];   // x as half
__device__ __half g_Bh[E_*K_];         // proj_w as half
__device__ float g_part[512*K_];       // per-(bc,half) partial pixel sums
__device__ float g_xm[NSEG*K_];        // segment-mean patch pixels
__device__ float g_mu[NSEG*E_];        // segment-mean embeddings (+proj_b)
__device__ float g_ctx[NSEG*E_];       // context vectors

// ---------------------------------------------------------------------------
static __device__ __forceinline__ uint32_t smem_u32(const void* p) {
    uint32_t a;
    asm("{ .reg .u64 t; cvta.to.shared.u64 t, %1; cvt.u32.u64 %0, t; }" : "=r"(a) : "l"(p));
    return a;
}
static __device__ __forceinline__ void cpa16(uint32_t dst, const void* src) {
    asm volatile("cp.async.cg.shared.global [%0], [%1], 16;" :: "r"(dst), "l"(src));
}
static __device__ __forceinline__ void cp_commit() {
    asm volatile("cp.async.commit_group;" ::: "memory");
}
static __device__ __forceinline__ void cp_wait2() {
    asm volatile("cp.async.wait_group 2;" ::: "memory");
}
static __device__ __forceinline__ void ldmx4(uint32_t* r, uint32_t a) {
    asm volatile("ldmatrix.sync.aligned.m8n8.x4.shared.b16 {%0,%1,%2,%3}, [%4];"
                 : "=r"(r[0]), "=r"(r[1]), "=r"(r[2]), "=r"(r[3]) : "r"(a));
}
static __device__ __forceinline__ void mma_f16(float* c, const uint32_t* a, const uint32_t* b) {
    asm volatile("mma.sync.aligned.m16n8k16.row.col.f32.f16.f16.f32 "
                 "{%0,%1,%2,%3}, {%4,%5,%6,%7}, {%8,%9}, {%0,%1,%2,%3};"
                 : "+f"(c[0]), "+f"(c[1]), "+f"(c[2]), "+f"(c[3])
                 : "r"(a[0]), "r"(a[1]), "r"(a[2]), "r"(a[3]), "r"(b[0]), "r"(b[1]));
}

// ---------------------------------------------------------------------------
// Launch 0/1: float -> half conversion (8 elems/thread)
__global__ void k_tohalf(const float* __restrict__ src, __half* __restrict__ dst) {
    size_t i = ((size_t)blockIdx.x * 256 + threadIdx.x) * 8;
    float4 v0 = *(const float4*)(src + i);
    float4 v1 = *(const float4*)(src + i + 4);
    __half2 h[4];
    h[0] = __floats2half2_rn(v0.x, v0.y);
    h[1] = __floats2half2_rn(v0.z, v0.w);
    h[2] = __floats2half2_rn(v1.x, v1.y);
    h[3] = __floats2half2_rn(v1.z, v1.w);
    *(uint4*)(dst + i) = *(uint4*)h;
}

// Launch 2: per-(bc, half-range) pixel sums from g_xh (half traffic of x).
__global__ void k_xbar() {
    int bc = blockIdx.x >> 1;
    int z  = blockIdx.x & 1;
    int t = threadIdx.x;
    int p = t >> 4, q = t & 15;
    const __half* base = g_xh + (size_t)bc * H_ * W_ + p * W_ + q;
    float s = 0.f;
    for (int hp = z*7; hp < z*7 + 7; hp++)
        #pragma unroll
        for (int wp = 0; wp < HP_; wp++)
            s += __half2float(base[(hp*P_)*W_ + wp*P_]);
    g_part[blockIdx.x * K_ + t] = s;
}

// Launch 3: segment counts + segment means -> g_xm. One block, 256 threads.
__global__ void k_seg(const int* __restrict__ cidx) {
    __shared__ float xs[NSEG*257];
    __shared__ int scnt[NSEG];
    __shared__ int segs[B_*C_];
    int t = threadIdx.x;
    if (t < NSEG) scnt[t] = 0;
    for (int i = t; i < NSEG*257; i += 256) xs[i] = 0.f;
    __syncthreads();
    if (t < B_*C_) {
        int s = cidx[t] & (NSEG-1);
        segs[t] = s;
        atomicAdd(&scnt[s], 1);
    }
    __syncthreads();
    // thread t owns pixel column t; serial over bc (lockstep, conflict-free banks)
    #pragma unroll 4
    for (int bc = 0; bc < B_*C_; bc++) {
        float v = g_part[(2*bc)*K_ + t] + g_part[(2*bc+1)*K_ + t];
        xs[segs[bc]*257 + t] += v;
    }
    __syncthreads();
    for (int i = t; i < NSEG*K_; i += 256) {
        int s = i >> 8;
        g_xm[i] = xs[s*257 + (i & 255)] / ((float)NPATCH * fmaxf((float)scnt[s], 1.f));
    }
}

// Launch 4: mu[s,e] = xm[s,:]@proj_w[e,:] + proj_b[e]. Grid 96 x 256 (block = 8 e x 32 s).
__global__ void k_mu2(const float* __restrict__ proj_w, const float* __restrict__ proj_b) {
    __shared__ float xs[NSEG*257];
    int t = threadIdx.x;
    for (int i = t; i < NSEG*K_; i += 256) xs[(i >> 8)*257 + (i & 255)] = g_xm[i];
    __syncthreads();
    int s = t & 31;
    int e = blockIdx.x * 8 + (t >> 5);
    const float* wrow = proj_w + (size_t)e * K_;   // uniform per warp
    float acc = 0.f;
    #pragma unroll 8
    for (int k = 0; k < K_; k++) acc += xs[s*257 + k] * wrow[k];
    g_mu[s*E_ + e] = acc + proj_b[e];
}

// Launch 5: ctx[s,e] = mu[s,:]@ctx_w[e,:] + ctx_b[e]. Grid 96 x 256.
__global__ void k_ctx3(const float* __restrict__ ctx_w, const float* __restrict__ ctx_b) {
    extern __shared__ float mus[];   // [32][769] padded
    int t = threadIdx.x;
    for (int i = t; i < NSEG*E_; i += 256) {
        int s = i / E_, f = i - s * E_;
        mus[s*769 + f] = g_mu[i];
    }
    __syncthreads();
    int s = t & 31;
    int e = blockIdx.x * 8 + (t >> 5);
    const float* crow = ctx_w + (size_t)e * E_;    // uniform per warp
    float acc = 0.f;
    #pragma unroll 8
    for (int f = 0; f < E_; f++) acc += mus[s*769 + f] * crow[f];
    g_ctx[s*E_ + e] = acc + ctx_b[e];
}

// ---------------------------------------------------------------------------
// Launch 6: FP16 mma.sync GEMM. CTA 128x128, K=256 in 4 chunks of 64.
// Stage: A 128x128B + B 128x128B = 32KB; 3 stages; XOR-swizzled 16B granules.
#define BM 128
#define BN 128
#define CK 64
#define NCH 4
#define ROWB 128
#define A_BYTES (BM*ROWB)     // 16384
#define STG_B (2*A_BYTES)     // 32768
#define NSTG 3

__global__ __launch_bounds__(256, 2)
void k_gemm_mma(const int* __restrict__ cidx, const float* __restrict__ proj_b,
                float* __restrict__ out) {
    extern __shared__ char dsm[];
    __shared__ int rowoff[BM];
    __shared__ int segrow[BM];

    int t = threadIdx.x;
    int lane = t & 31;
    int wid = t >> 5;
    int wm = wid >> 1, wn = wid & 1;
    int m0 = blockIdx.y * BM;
    int e0 = blockIdx.x * BN;
    uint32_t base_u = smem_u32(dsm);

    if (t < BM) {
        int m  = m0 + t;
        int b  = m / (C_ * NPATCH);
        int n  = m - b * (C_ * NPATCH);
        int c  = n / NPATCH;
        int r  = n - c * NPATCH;
        int hp = r / HP_;
        int wp = r - hp * HP_;
        rowoff[t] = ((b * C_ + c) * H_ + hp * P_) * W_ + wp * P_;
        segrow[t] = cidx[m / NPATCH] & (NSEG-1);
    }
    __syncthreads();

    // chunk c covers local k = 0..63 : pixel rows 4c..4c+3, 16 halves each.
    auto issue = [&](int c, int st) {
        uint32_t sb = base_u + st * STG_B;
        #pragma unroll
        for (int j = 0; j < 4; j++) {
            int idx = t + 256 * j;
            int row = idx >> 3, g = idx & 7;
            uint32_t sw = (uint32_t)((g ^ (row & 7)) << 4);
            const __half* pa = g_xh + rowoff[row] + (c*4 + (g >> 1)) * W_ + (g & 1) * 8;
            cpa16(sb + row * ROWB + sw, pa);
            const __half* pb = g_Bh + (size_t)(e0 + row) * K_ + c * CK + g * 8;
            cpa16(sb + A_BYTES + row * ROWB + sw, pb);
        }
    };

    issue(0, 0); cp_commit();
    issue(1, 1); cp_commit();
    issue(2, 2); cp_commit();

    float acc[2][8][4];
    #pragma unroll
    for (int i = 0; i < 2; i++)
        #pragma unroll
        for (int j = 0; j < 8; j++)
            #pragma unroll
            for (int s = 0; s < 4; s++) acc[i][j][s] = 0.f;

    int gid = lane >> 2, tid = lane & 3;

    for (int c = 0; c < NCH; c++) {
        int st = c % NSTG;
        cp_wait2();
        __syncthreads();

        uint32_t sa = base_u + st * STG_B;
        uint32_t sbb = sa + A_BYTES;
        #pragma unroll
        for (int ks = 0; ks < 4; ks++) {
            uint32_t a[2][4];
            #pragma unroll
            for (int i = 0; i < 2; i++) {
                int r = wm * 32 + i * 16 + (lane & 15);
                int g = 2 * ks + (lane >> 4);
                ldmx4(a[i], sa + r * ROWB + ((g ^ (r & 7)) << 4));
            }
            uint32_t b[8][2];
            #pragma unroll
            for (int j = 0; j < 4; j++) {
                int nt = 2 * j + ((lane >> 4) & 1);
                int n = wn * 64 + nt * 8 + (lane & 7);
                int g = 2 * ks + ((lane >> 3) & 1);
                uint32_t r4[4];
                ldmx4(r4, sbb + n * ROWB + ((g ^ (n & 7)) << 4));
                b[2*j][0] = r4[0]; b[2*j][1] = r4[1];
                b[2*j+1][0] = r4[2]; b[2*j+1][1] = r4[3];
            }
            #pragma unroll
            for (int i = 0; i < 2; i++)
                #pragma unroll
                for (int j = 0; j < 8; j++)
                    mma_f16(acc[i][j], a[i], b[j]);
        }
        __syncthreads();
        if (c + 3 < NCH) issue(c + 3, st);
        cp_commit();   // empty groups keep wait_group arithmetic uniform (in-order retire)
    }

    // Epilogue: c0,c1 @ row gid; c2,c3 @ row gid+8; cols 2*tid
    #pragma unroll
    for (int i = 0; i < 2; i++) {
        #pragma unroll
        for (int h = 0; h < 2; h++) {
            int mloc = wm * 32 + i * 16 + h * 8 + gid;
            const float* cr = g_ctx + (size_t)segrow[mloc] * E_;
            float* orow = out + (size_t)(m0 + mloc) * E_;
            #pragma unroll
            for (int j = 0; j < 8; j++) {
                int col = e0 + wn * 64 + j * 8 + tid * 2;
                float2 bv = *(const float2*)(proj_b + col);
                float2 cv = *(const float2*)(cr + col);
                float2 o;
                o.x = acc[i][j][h*2+0] + bv.x + cv.x;
                o.y = acc[i][j][h*2+1] + bv.y + cv.y;
                *(float2*)(orow + col) = o;
            }
        }
    }
}

// ---------------------------------------------------------------------------
extern "C" void kernel_launch(void* const* d_in, const int* in_sizes, int n_in,
                              void* d_out, int out_size) {
    const float* x      = (const float*)d_in[0];
    const int*   cidx   = (const int*)d_in[1];
    const float* proj_w = (const float*)d_in[2];
    const float* proj_b = (const float*)d_in[3];
    const float* ctx_w  = (const float*)d_in[4];
    const float* ctx_b  = (const float*)d_in[5];
    float*       out    = (float*)d_out;

    __half* xh; cudaGetSymbolAddress((void**)&xh, g_xh);
    __half* bh; cudaGetSymbolAddress((void**)&bh, g_Bh);

    k_tohalf<<<(B_*C_*H_*W_)/2048, 256>>>(x, xh);          // 0
    k_tohalf<<<(E_*K_)/2048, 256>>>(proj_w, bh);           // 1
    k_xbar<<<2*B_*C_, 256>>>();                            // 2
    k_seg<<<1, 256>>>(cidx);                               // 3
    k_mu2<<<E_/8, 256>>>(proj_w, proj_b);                  // 4

    cudaFuncSetAttribute(k_ctx3, cudaFuncAttributeMaxDynamicSharedMemorySize, NSEG*769*4);
    k_ctx3<<<E_/8, 256, NSEG*769*4>>>(ctx_w, ctx_b);       // 5

    cudaFuncSetAttribute(k_gemm_mma, cudaFuncAttributeMaxDynamicSharedMemorySize, NSTG*STG_B);
    k_gemm_mma<<<dim3(E_/BN, M_/BM), 256, NSTG*STG_B>>>(cidx, proj_b, out);  // 6
}

// round 10
// speedup vs baseline: 3.1868x; 1.0658x over previous
#include <cuda_runtime.h>
#include <cuda_fp16.h>
#include <cstdint>

// Problem constants
#define B_      32
#define C_      8
#define H_      224
#define W_      224
#define E_      768
#define P_      16
#define HP_     14
#define NPATCH  196
#define NSEG    32
#define K_      256
#define M_      (B_*C_*NPATCH)  // 50176

// Static device scratch
__device__ __half g_xh[B_*C_*H_*W_];   // x as half
__device__ __half g_Bh[E_*K_];         // proj_w as half
__device__ float g_part[512*K_];       // per-(bc,half) partial pixel sums
__device__ float g_xm[NSEG*K_];        // segment-mean patch pixels
__device__ float g_mu[NSEG*E_];        // segment-mean embeddings (+proj_b)
__device__ float g_ctx[NSEG*E_];       // context vectors

// ---------------------------------------------------------------------------
static __device__ __forceinline__ uint32_t smem_u32(const void* p) {
    uint32_t a;
    asm("{ .reg .u64 t; cvta.to.shared.u64 t, %1; cvt.u32.u64 %0, t; }" : "=r"(a) : "l"(p));
    return a;
}
static __device__ __forceinline__ void cpa16(uint32_t dst, const void* src) {
    asm volatile("cp.async.cg.shared.global [%0], [%1], 16;" :: "r"(dst), "l"(src));
}
static __device__ __forceinline__ void cp_commit() {
    asm volatile("cp.async.commit_group;" ::: "memory");
}
static __device__ __forceinline__ void cp_wait2() {
    asm volatile("cp.async.wait_group 2;" ::: "memory");
}
static __device__ __forceinline__ void ldmx4(uint32_t* r, uint32_t a) {
    asm volatile("ldmatrix.sync.aligned.m8n8.x4.shared.b16 {%0,%1,%2,%3}, [%4];"
                 : "=r"(r[0]), "=r"(r[1]), "=r"(r[2]), "=r"(r[3]) : "r"(a));
}
static __device__ __forceinline__ void mma_f16(float* c, const uint32_t* a, const uint32_t* b) {
    asm volatile("mma.sync.aligned.m16n8k16.row.col.f32.f16.f16.f32 "
                 "{%0,%1,%2,%3}, {%4,%5,%6,%7}, {%8,%9}, {%0,%1,%2,%3};"
                 : "+f"(c[0]), "+f"(c[1]), "+f"(c[2]), "+f"(c[3])
                 : "r"(a[0]), "r"(a[1]), "r"(a[2]), "r"(a[3]), "r"(b[0]), "r"(b[1]));
}

// ---------------------------------------------------------------------------
// Launch 0/1: float -> half conversion (8 elems/thread)
__global__ void k_tohalf(const float* __restrict__ src, __half* __restrict__ dst) {
    size_t i = ((size_t)blockIdx.x * 256 + threadIdx.x) * 8;
    float4 v0 = *(const float4*)(src + i);
    float4 v1 = *(const float4*)(src + i + 4);
    __half2 h[4];
    h[0] = __floats2half2_rn(v0.x, v0.y);
    h[1] = __floats2half2_rn(v0.z, v0.w);
    h[2] = __floats2half2_rn(v1.x, v1.y);
    h[3] = __floats2half2_rn(v1.z, v1.w);
    *(uint4*)(dst + i) = *(uint4*)h;
}

// Launch 2: per-(bc, half-range) pixel sums from g_xh.
__global__ void k_xbar() {
    int bc = blockIdx.x >> 1;
    int z  = blockIdx.x & 1;
    int t = threadIdx.x;
    int p = t >> 4, q = t & 15;
    const __half* base = g_xh + (size_t)bc * H_ * W_ + p * W_ + q;
    float s = 0.f;
    for (int hp = z*7; hp < z*7 + 7; hp++)
        #pragma unroll
        for (int wp = 0; wp < HP_; wp++)
            s += __half2float(base[(hp*P_)*W_ + wp*P_]);
    g_part[blockIdx.x * K_ + t] = s;
}

// Launch 3: gather-based segment means. One block per segment (grid 32).
__global__ void k_seg(const int* __restrict__ cidx) {
    __shared__ int list[B_*C_];
    __shared__ int s_cnt;
    int t = threadIdx.x;
    int seg = blockIdx.x;
    if (t == 0) {
        int c = 0;
        #pragma unroll 4
        for (int bc = 0; bc < B_*C_; bc++)
            if ((cidx[bc] & (NSEG-1)) == seg) list[c++] = bc;
        s_cnt = c;
    }
    __syncthreads();
    int cnt = s_cnt;
    float s = 0.f;
    for (int j = 0; j < cnt; j++) {      // independent coalesced loads, high MLP
        int bc = list[j];
        s += g_part[(2*bc)*K_ + t] + g_part[(2*bc+1)*K_ + t];
    }
    g_xm[seg*K_ + t] = s / ((float)NPATCH * fmaxf((float)cnt, 1.f));
}

// Launch 4: mu[s,e] = xm[s,:]@proj_w[e,:] + proj_b[e]. Grid 96 x 256 (block = 8 e x 32 s).
__global__ void k_mu2(const float* __restrict__ proj_w, const float* __restrict__ proj_b) {
    __shared__ float xs[NSEG*257];
    int t = threadIdx.x;
    for (int i = t; i < NSEG*K_; i += 256) xs[(i >> 8)*257 + (i & 255)] = g_xm[i];
    __syncthreads();
    int s = t & 31;
    int e = blockIdx.x * 8 + (t >> 5);
    const float* wrow = proj_w + (size_t)e * K_;   // uniform per warp
    float acc = 0.f;
    #pragma unroll 8
    for (int k = 0; k < K_; k++) acc += xs[s*257 + k] * wrow[k];
    g_mu[s*E_ + e] = acc + proj_b[e];
}

// Launch 5: ctx[s,e] = mu[s,:]@ctx_w[e,:] + ctx_b[e]. Grid 96 x 256.
__global__ void k_ctx3(const float* __restrict__ ctx_w, const float* __restrict__ ctx_b) {
    extern __shared__ float mus[];   // [32][769] padded
    int t = threadIdx.x;
    for (int i = t; i < NSEG*E_; i += 256) {
        int s = i / E_, f = i - s * E_;
        mus[s*769 + f] = g_mu[i];
    }
    __syncthreads();
    int s = t & 31;
    int e = blockIdx.x * 8 + (t >> 5);
    const float* crow = ctx_w + (size_t)e * E_;    // uniform per warp
    float acc = 0.f;
    #pragma unroll 8
    for (int f = 0; f < E_; f++) acc += mus[s*769 + f] * crow[f];
    g_ctx[s*E_ + e] = acc + ctx_b[e];
}

// ---------------------------------------------------------------------------
// Launch 6: FP16 mma.sync GEMM. CTA 128x128, K=256 in 4 chunks of 64.
// Stage: A 128x128B + B 128x128B = 32KB; 3 stages; XOR-swizzled 16B granules.
#define BM 128
#define BN 128
#define CK 64
#define NCH 4
#define ROWB 128
#define A_BYTES (BM*ROWB)     // 16384
#define STG_B (2*A_BYTES)     // 32768
#define NSTG 3

__global__ __launch_bounds__(256, 2)
void k_gemm_mma(const int* __restrict__ cidx, const float* __restrict__ proj_b,
                float* __restrict__ out) {
    extern __shared__ char dsm[];
    __shared__ int rowoff[BM];
    __shared__ int segrow[BM];

    int t = threadIdx.x;
    int lane = t & 31;
    int wid = t >> 5;
    int wm = wid >> 1, wn = wid & 1;
    int m0 = blockIdx.y * BM;
    int e0 = blockIdx.x * BN;
    uint32_t base_u = smem_u32(dsm);

    if (t < BM) {
        int m  = m0 + t;
        int b  = m / (C_ * NPATCH);
        int n  = m - b * (C_ * NPATCH);
        int c  = n / NPATCH;
        int r  = n - c * NPATCH;
        int hp = r / HP_;
        int wp = r - hp * HP_;
        rowoff[t] = ((b * C_ + c) * H_ + hp * P_) * W_ + wp * P_;
        segrow[t] = cidx[m / NPATCH] & (NSEG-1);
    }
    __syncthreads();

    // chunk c covers local k = 0..63 : pixel rows 4c..4c+3, 16 halves each.
    auto issue = [&](int c, int st) {
        uint32_t sb = base_u + st * STG_B;
        #pragma unroll
        for (int j = 0; j < 4; j++) {
            int idx = t + 256 * j;
            int row = idx >> 3, g = idx & 7;
            uint32_t sw = (uint32_t)((g ^ (row & 7)) << 4);
            const __half* pa = g_xh + rowoff[row] + (c*4 + (g >> 1)) * W_ + (g & 1) * 8;
            cpa16(sb + row * ROWB + sw, pa);
            const __half* pb = g_Bh + (size_t)(e0 + row) * K_ + c * CK + g * 8;
            cpa16(sb + A_BYTES + row * ROWB + sw, pb);
        }
    };

    issue(0, 0); cp_commit();
    issue(1, 1); cp_commit();
    issue(2, 2); cp_commit();

    float acc[2][8][4];
    #pragma unroll
    for (int i = 0; i < 2; i++)
        #pragma unroll
        for (int j = 0; j < 8; j++)
            #pragma unroll
            for (int s = 0; s < 4; s++) acc[i][j][s] = 0.f;

    int gid = lane >> 2, tid = lane & 3;

    for (int c = 0; c < NCH; c++) {
        int st = c % NSTG;
        cp_wait2();
        __syncthreads();

        uint32_t sa = base_u + st * STG_B;
        uint32_t sbb = sa + A_BYTES;
        #pragma unroll
        for (int ks = 0; ks < 4; ks++) {
            uint32_t a[2][4];
            #pragma unroll
            for (int i = 0; i < 2; i++) {
                int r = wm * 32 + i * 16 + (lane & 15);
                int g = 2 * ks + (lane >> 4);
                ldmx4(a[i], sa + r * ROWB + ((g ^ (r & 7)) << 4));
            }
            uint32_t b[8][2];
            #pragma unroll
            for (int j = 0; j < 4; j++) {
                int nt = 2 * j + ((lane >> 4) & 1);
                int n = wn * 64 + nt * 8 + (lane & 7);
                int g = 2 * ks + ((lane >> 3) & 1);
                uint32_t r4[4];
                ldmx4(r4, sbb + n * ROWB + ((g ^ (n & 7)) << 4));
                b[2*j][0] = r4[0]; b[2*j][1] = r4[1];
                b[2*j+1][0] = r4[2]; b[2*j+1][1] = r4[3];
            }
            #pragma unroll
            for (int i = 0; i < 2; i++)
                #pragma unroll
                for (int j = 0; j < 8; j++)
                    mma_f16(acc[i][j], a[i], b[j]);
        }
        __syncthreads();
        if (c + 3 < NCH) issue(c + 3, st);
        cp_commit();   // empty groups keep wait_group arithmetic uniform (in-order retire)
    }

    // Epilogue: c0,c1 @ row gid; c2,c3 @ row gid+8; cols 2*tid
    #pragma unroll
    for (int i = 0; i < 2; i++) {
        #pragma unroll
        for (int h = 0; h < 2; h++) {
            int mloc = wm * 32 + i * 16 + h * 8 + gid;
            const float* cr = g_ctx + (size_t)segrow[mloc] * E_;
            float* orow = out + (size_t)(m0 + mloc) * E_;
            #pragma unroll
            for (int j = 0; j < 8; j++) {
                int col = e0 + wn * 64 + j * 8 + tid * 2;
                float2 bv = *(const float2*)(proj_b + col);
                float2 cv = *(const float2*)(cr + col);
                float2 o;
                o.x = acc[i][j][h*2+0] + bv.x + cv.x;
                o.y = acc[i][j][h*2+1] + bv.y + cv.y;
                *(float2*)(orow + col) = o;
            }
        }
    }
}

// ---------------------------------------------------------------------------
extern "C" void kernel_launch(void* const* d_in, const int* in_sizes, int n_in,
                              void* d_out, int out_size) {
    const float* x      = (const float*)d_in[0];
    const int*   cidx   = (const int*)d_in[1];
    const float* proj_w = (const float*)d_in[2];
    const float* proj_b = (const float*)d_in[3];
    const float* ctx_w  = (const float*)d_in[4];
    const float* ctx_b  = (const float*)d_in[5];
    float*       out    = (float*)d_out;

    __half* xh; cudaGetSymbolAddress((void**)&xh, g_xh);
    __half* bh; cudaGetSymbolAddress((void**)&bh, g_Bh);

    k_tohalf<<<(B_*C_*H_*W_)/2048, 256>>>(x, xh);          // 0
    k_tohalf<<<(E_*K_)/2048, 256>>>(proj_w, bh);           // 1
    k_xbar<<<2*B_*C_, 256>>>();                            // 2
    k_seg<<<NSEG, 256>>>(cidx);                            // 3
    k_mu2<<<E_/8, 256>>>(proj_w, proj_b);                  // 4

    cudaFuncSetAttribute(k_ctx3, cudaFuncAttributeMaxDynamicSharedMemorySize, NSEG*769*4);
    k_ctx3<<<E_/8, 256, NSEG*769*4>>>(ctx_w, ctx_b);       // 5

    cudaFuncSetAttribute(k_gemm_mma, cudaFuncAttributeMaxDynamicSharedMemorySize, NSTG*STG_B);
    k_gemm_mma<<<dim3(E_/BN, M_/BM), 256, NSTG*STG_B>>>(cidx, proj_b, out);  // 6
}